// round 1
// baseline (speedup 1.0000x reference)
#include <cuda_runtime.h>
#include <cuda_bf16.h>

// Problem constants
#define L_MAX       3
#define NUM_SHELLS  4
#define N_SH        16      // 1+3+5+7
#define N_MONO      20
#define BATCH       8
#define NV          2048
#define NP          32
#define PTS_TOTAL   (BATCH * NV * NP)      // 524288
#define PTS_PER_B   (NV * NP)              // 65536
#define OUT_PER_PT  (N_SH * NUM_SHELLS)    // 64

// Accumulator for sum over v of ml[b][l][s]  (8 * 16 floats)
__device__ float g_acc[BATCH * 16];

// ---------------------------------------------------------------------------
// Shared per-point math: monomials -> sh[16], gaussian shells[4] (normalized,
// masked by dist<=1). Y supplied as float4[80] in shared memory.
// Monomial order matches sorted((i,j,k)) with exponents on (x,y,z):
//  (0,0,0),(0,0,1),(0,0,2),(0,0,3),(0,1,0),(0,1,1),(0,1,2),(0,2,0),(0,2,1),
//  (0,3,0),(1,0,0),(1,0,1),(1,0,2),(1,1,0),(1,1,1),(1,2,0),(2,0,0),(2,0,1),
//  (2,1,0),(3,0,0)
// ---------------------------------------------------------------------------
__device__ __forceinline__ void compute_point(
    float x, float y, float z,
    const float4* __restrict__ Ys,
    float sh[N_SH], float shell[NUM_SHELLS])
{
    float d2   = x * x + y * y + z * z;
    float dist = sqrtf(d2);
    float inv  = 1.0f / fmaxf(dist, 1e-6f);
    float nx = -x * inv, ny = -y * inv, nz = -z * inv;
    float nx2 = nx * nx, ny2 = ny * ny, nz2 = nz * nz;

    float mono[N_MONO];
    mono[0]  = 1.0f;
    mono[1]  = nz;
    mono[2]  = nz2;
    mono[3]  = nz2 * nz;
    mono[4]  = ny;
    mono[5]  = ny * nz;
    mono[6]  = ny * nz2;
    mono[7]  = ny2;
    mono[8]  = ny2 * nz;
    mono[9]  = ny2 * ny;
    mono[10] = nx;
    mono[11] = nx * nz;
    mono[12] = nx * nz2;
    mono[13] = nx * ny;
    mono[14] = nx * ny * nz;
    mono[15] = nx * ny2;
    mono[16] = nx2;
    mono[17] = nx2 * nz;
    mono[18] = nx2 * ny;
    mono[19] = nx2 * nx;

#pragma unroll
    for (int i = 0; i < N_SH; i++) {
        float s = 0.0f;
#pragma unroll
        for (int j4 = 0; j4 < 5; j4++) {
            float4 yv = Ys[i * 5 + j4];
            s += yv.x * mono[j4 * 4 + 0];
            s += yv.y * mono[j4 * 4 + 1];
            s += yv.z * mono[j4 * 4 + 2];
            s += yv.w * mono[j4 * 4 + 3];
        }
        sh[i] = s;
    }

    float ssum = 0.0f;
#pragma unroll
    for (int s = 0; s < NUM_SHELLS; s++) {
        float r  = dist - (float)s * (1.0f / 3.0f);
        shell[s] = expf(-16.0f * r * r);
        ssum    += shell[s];
    }
    float sinv = 1.0f / fmaxf(ssum, 1e-6f);
    float mask = (dist <= 1.0f) ? sinv : 0.0f;
#pragma unroll
    for (int s = 0; s < NUM_SHELLS; s++) shell[s] *= mask;
}

// ---------------------------------------------------------------------------
// Kernel 0: zero the accumulator
// ---------------------------------------------------------------------------
__global__ void sh_zero_acc()
{
    g_acc[threadIdx.x] = 0.0f;
}

// ---------------------------------------------------------------------------
// Kernel 1: per-(b,v) reduction. One warp per (b,v); lane = point p.
//   contrib[l][s] = shell_s^2 * sum_{i in degree l} sh_i^2
//   warp-reduce over p, sqrt, accumulate over v into g_acc[b][l*4+s].
// Block = 256 threads = 8 warps = 8 consecutive v (same b, since 8 | 2048).
// ---------------------------------------------------------------------------
__global__ __launch_bounds__(256) void sh_reduce_kernel(
    const float* __restrict__ patches, const float* __restrict__ Y)
{
    __shared__ float4 Ys[80];
    __shared__ float sacc[16];

    int tid = threadIdx.x;
    for (int k = tid; k < 80; k += 256) Ys[k] = ((const float4*)Y)[k];
    if (tid < 16) sacc[tid] = 0.0f;
    __syncthreads();

    int warp = tid >> 5;
    int lane = tid & 31;
    int vg   = blockIdx.x * 8 + warp;       // global b*NV + v
    int b    = vg >> 11;                    // / 2048
    long pt  = (long)vg * NP + lane;

    float x = patches[pt * 3 + 0];
    float y = patches[pt * 3 + 1];
    float z = patches[pt * 3 + 2];

    float sh[N_SH], shell[NUM_SHELLS];
    compute_point(x, y, z, Ys, sh, shell);

    float q[4];
    q[0] = sh[0] * sh[0];
    q[1] = sh[1] * sh[1] + sh[2] * sh[2] + sh[3] * sh[3];
    q[2] = sh[4] * sh[4] + sh[5] * sh[5] + sh[6] * sh[6] + sh[7] * sh[7] + sh[8] * sh[8];
    q[3] = sh[9] * sh[9] + sh[10] * sh[10] + sh[11] * sh[11] + sh[12] * sh[12]
         + sh[13] * sh[13] + sh[14] * sh[14] + sh[15] * sh[15];

    float red[16];
#pragma unroll
    for (int l = 0; l < 4; l++) {
#pragma unroll
        for (int s = 0; s < 4; s++)
            red[l * 4 + s] = shell[s] * shell[s] * q[l];
    }

    // Reduce each of the 16 values across the warp; lane k keeps value k.
    float myval = 0.0f;
#pragma unroll
    for (int k = 0; k < 16; k++) {
        float v = red[k];
#pragma unroll
        for (int off = 16; off > 0; off >>= 1)
            v += __shfl_xor_sync(0xffffffffu, v, off);
        if (lane == k) myval = sqrtf(v);
    }
    if (lane < 16) atomicAdd(&sacc[lane], myval);
    __syncthreads();
    if (tid < 16) atomicAdd(&g_acc[b * 16 + tid], sacc[tid]);
}

// ---------------------------------------------------------------------------
// Kernel 2: recompute per-point sh/shells, scale by 1/norm, write 64 floats
// per point. Staged through padded shared memory for fully coalesced stores.
// Block = 128 threads = 128 points (all same b: 512 blocks per b).
// ---------------------------------------------------------------------------
__global__ __launch_bounds__(128) void sh_write_kernel(
    const float* __restrict__ patches, const float* __restrict__ Y,
    float* __restrict__ out)
{
    __shared__ float4 Ys[80];
    __shared__ float invn[16];
    __shared__ float stage[128 * 65];   // stride 65 -> conflict-free

    int tid    = threadIdx.x;
    int ptbase = blockIdx.x * 128;
    int b      = ptbase >> 16;          // / 65536 points per batch

    for (int k = tid; k < 80; k += 128) Ys[k] = ((const float4*)Y)[k];
    if (tid < 16)
        invn[tid] = 1.0f / fmaxf(g_acc[b * 16 + tid] * (1.0f / (float)NV), 1e-8f);
    __syncthreads();

    int pt  = ptbase + tid;
    float x = patches[(long)pt * 3 + 0];
    float y = patches[(long)pt * 3 + 1];
    float z = patches[(long)pt * 3 + 2];

    float sh[N_SH], shell[NUM_SHELLS];
    compute_point(x, y, z, Ys, sh, shell);

    // a[l][s] = shell_s * invn[l*4+s]  (16 LDS once, reused for all i)
    float a[4][4];
#pragma unroll
    for (int l = 0; l < 4; l++)
#pragma unroll
        for (int s = 0; s < 4; s++)
            a[l][s] = shell[s] * invn[l * 4 + s];

    float* st = &stage[tid * 65];
#pragma unroll
    for (int i = 0; i < N_SH; i++) {
        const int l = (i == 0) ? 0 : (i < 4) ? 1 : (i < 9) ? 2 : 3;
#pragma unroll
        for (int s = 0; s < 4; s++)
            st[i * 4 + s] = sh[i] * a[l][s];
    }
    __syncthreads();

    // Coalesced copy: 128 pts * 64 floats = 8192 floats, 64 per thread.
    float* ob = out + (long)ptbase * OUT_PER_PT;
#pragma unroll 8
    for (int k = 0; k < 64; k++) {
        int idx   = k * 128 + tid;
        int point = idx >> 6;
        int j     = idx & 63;
        ob[idx]   = stage[point * 65 + j];
    }
}

// ---------------------------------------------------------------------------
extern "C" void kernel_launch(void* const* d_in, const int* in_sizes, int n_in,
                              void* d_out, int out_size)
{
    const float* patches = (const float*)d_in[0];
    const float* Y       = (const float*)d_in[1];
    float*       out     = (float*)d_out;

    sh_zero_acc<<<1, BATCH * 16>>>();
    sh_reduce_kernel<<<(BATCH * NV) / 8, 256>>>(patches, Y);
    sh_write_kernel<<<PTS_TOTAL / 128, 128>>>(patches, Y, out);
}

// round 2
// speedup vs baseline: 1.1601x; 1.1601x over previous
#include <cuda_runtime.h>
#include <cuda_bf16.h>

// Problem constants
#define L_MAX       3
#define NUM_SHELLS  4
#define N_SH        16      // 1+3+5+7
#define N_MONO      20
#define BATCH       8
#define NV          2048
#define NP          32
#define PTS_TOTAL   (BATCH * NV * NP)      // 524288
#define OUT_PER_PT  (N_SH * NUM_SHELLS)    // 64

// Accumulator for sum over v of ml[b][l][s]  (8 * 16 floats)
__device__ float g_acc[BATCH * 16];

// ---------------------------------------------------------------------------
// Per-point math: monomials -> sh[16], gaussian shells[4] (normalized,
// masked by dist<=1). Y supplied as float4[80] in shared memory.
// Monomial order matches sorted((i,j,k)) with exponents applied to (x,y,z):
//  (0,0,0),(0,0,1),(0,0,2),(0,0,3),(0,1,0),(0,1,1),(0,1,2),(0,2,0),(0,2,1),
//  (0,3,0),(1,0,0),(1,0,1),(1,0,2),(1,1,0),(1,1,1),(1,2,0),(2,0,0),(2,0,1),
//  (2,1,0),(3,0,0)
// ---------------------------------------------------------------------------
__device__ __forceinline__ void compute_point(
    float x, float y, float z,
    const float4* __restrict__ Ys,
    float sh[N_SH], float shell[NUM_SHELLS])
{
    float d2   = x * x + y * y + z * z;
    float inv  = rsqrtf(fmaxf(d2, 1e-12f));   // == 1/dist (dist >= 1e-6 branch)
    float dist = d2 * inv;                     // == sqrt(d2)
    float nx = -x * inv, ny = -y * inv, nz = -z * inv;
    float nx2 = nx * nx, ny2 = ny * ny, nz2 = nz * nz;

    float mono[N_MONO];
    mono[0]  = 1.0f;
    mono[1]  = nz;
    mono[2]  = nz2;
    mono[3]  = nz2 * nz;
    mono[4]  = ny;
    mono[5]  = ny * nz;
    mono[6]  = ny * nz2;
    mono[7]  = ny2;
    mono[8]  = ny2 * nz;
    mono[9]  = ny2 * ny;
    mono[10] = nx;
    mono[11] = nx * nz;
    mono[12] = nx * nz2;
    mono[13] = nx * ny;
    mono[14] = nx * ny * nz;
    mono[15] = nx * ny2;
    mono[16] = nx2;
    mono[17] = nx2 * nz;
    mono[18] = nx2 * ny;
    mono[19] = nx2 * nx;

#pragma unroll
    for (int i = 0; i < N_SH; i++) {
        float s = 0.0f;
#pragma unroll
        for (int j4 = 0; j4 < 5; j4++) {
            float4 yv = Ys[i * 5 + j4];
            s += yv.x * mono[j4 * 4 + 0];
            s += yv.y * mono[j4 * 4 + 1];
            s += yv.z * mono[j4 * 4 + 2];
            s += yv.w * mono[j4 * 4 + 3];
        }
        sh[i] = s;
    }

    float ssum = 0.0f;
#pragma unroll
    for (int s = 0; s < NUM_SHELLS; s++) {
        float r  = dist - (float)s * (1.0f / 3.0f);
        shell[s] = __expf(-16.0f * r * r);
        ssum    += shell[s];
    }
    float sinv = __fdividef(1.0f, fmaxf(ssum, 1e-6f));
    float mask = (dist <= 1.0f) ? sinv : 0.0f;
#pragma unroll
    for (int s = 0; s < NUM_SHELLS; s++) shell[s] *= mask;
}

// ---------------------------------------------------------------------------
// Kernel 0: zero the accumulator
// ---------------------------------------------------------------------------
__global__ void sh_zero_acc()
{
    g_acc[threadIdx.x] = 0.0f;
}

// ---------------------------------------------------------------------------
// Kernel 1: per-(b,v) reduction. One warp per (b,v); lane = point p.
//   red[l*4+s] = shell_s^2 * sum_{i in degree l} sh_i^2
// Multi-value butterfly: reduce 16 values across 32 lanes in 16 shuffles.
// After the last step, lanes (2k, 2k+1) both hold total for value k=lane>>1.
// ---------------------------------------------------------------------------
__global__ __launch_bounds__(256) void sh_reduce_kernel(
    const float* __restrict__ patches, const float* __restrict__ Y)
{
    __shared__ float4 Ys[80];
    __shared__ float sacc[16];

    int tid = threadIdx.x;
    for (int k = tid; k < 80; k += 256) Ys[k] = ((const float4*)Y)[k];
    if (tid < 16) sacc[tid] = 0.0f;
    __syncthreads();

    int warp = tid >> 5;
    int lane = tid & 31;
    int vg   = blockIdx.x * 8 + warp;       // global b*NV + v
    int b    = vg >> 11;                    // / 2048
    long pt  = (long)vg * NP + lane;

    float x = patches[pt * 3 + 0];
    float y = patches[pt * 3 + 1];
    float z = patches[pt * 3 + 2];

    float sh[N_SH], shell[NUM_SHELLS];
    compute_point(x, y, z, Ys, sh, shell);

    float q0 = sh[0] * sh[0];
    float q1 = sh[1] * sh[1] + sh[2] * sh[2] + sh[3] * sh[3];
    float q2 = sh[4] * sh[4] + sh[5] * sh[5] + sh[6] * sh[6] + sh[7] * sh[7]
             + sh[8] * sh[8];
    float q3 = sh[9] * sh[9] + sh[10] * sh[10] + sh[11] * sh[11]
             + sh[12] * sh[12] + sh[13] * sh[13] + sh[14] * sh[14]
             + sh[15] * sh[15];

    float v[16];
    {
        float s2[4];
#pragma unroll
        for (int s = 0; s < 4; s++) s2[s] = shell[s] * shell[s];
#pragma unroll
        for (int s = 0; s < 4; s++) {
            v[0 * 4 + s]  = s2[s] * q0;
            v[1 * 4 + s]  = s2[s] * q1;
            v[2 * 4 + s]  = s2[s] * q2;
            v[3 * 4 + s]  = s2[s] * q3;
        }
    }

    // Step 1: offset 16, 16 vals -> 8  (8 shuffles)
#pragma unroll
    for (int k = 0; k < 8; k++) {
        bool hi    = (lane & 16) != 0;
        float send = hi ? v[k] : v[k + 8];
        float keep = hi ? v[k + 8] : v[k];
        v[k] = keep + __shfl_xor_sync(0xffffffffu, send, 16);
    }
    // Step 2: offset 8, 8 -> 4
#pragma unroll
    for (int k = 0; k < 4; k++) {
        bool hi    = (lane & 8) != 0;
        float send = hi ? v[k] : v[k + 4];
        float keep = hi ? v[k + 4] : v[k];
        v[k] = keep + __shfl_xor_sync(0xffffffffu, send, 8);
    }
    // Step 3: offset 4, 4 -> 2
#pragma unroll
    for (int k = 0; k < 2; k++) {
        bool hi    = (lane & 4) != 0;
        float send = hi ? v[k] : v[k + 2];
        float keep = hi ? v[k + 2] : v[k];
        v[k] = keep + __shfl_xor_sync(0xffffffffu, send, 4);
    }
    // Step 4: offset 2, 2 -> 1
    {
        bool hi    = (lane & 2) != 0;
        float send = hi ? v[0] : v[1];
        float keep = hi ? v[1] : v[0];
        v[0] = keep + __shfl_xor_sync(0xffffffffu, send, 2);
    }
    // Step 5: offset 1 (both lanes of the pair end with the total)
    v[0] += __shfl_xor_sync(0xffffffffu, v[0], 1);

    // Value index held by this lane pair. Mapping derived from the splits:
    //   idx = bit1(lane) + 2*bit2 + 4*bit3 + 8*bit4 = lane >> 1
    if ((lane & 1) == 0)
        atomicAdd(&sacc[lane >> 1], sqrtf(v[0]));

    __syncthreads();
    if (tid < 16) atomicAdd(&g_acc[b * 16 + tid], sacc[tid]);
}

// ---------------------------------------------------------------------------
// Kernel 2: recompute per-point sh/shells, scale by 1/norm, write 64 floats
// per point. float4 staging through padded shared (stride 17 float4 ->
// conflict-free both directions), then fully coalesced float4 stores.
// Block = 128 threads = 128 points (all same b: 512 blocks per b).
// ---------------------------------------------------------------------------
__global__ __launch_bounds__(128) void sh_write_kernel(
    const float* __restrict__ patches, const float* __restrict__ Y,
    float* __restrict__ out)
{
    __shared__ float4 Ys[80];
    __shared__ float  invn[16];
    __shared__ float4 stage4[128 * 17];

    int tid    = threadIdx.x;
    int ptbase = blockIdx.x * 128;
    int b      = ptbase >> 16;          // / 65536 points per batch

    for (int k = tid; k < 80; k += 128) Ys[k] = ((const float4*)Y)[k];
    if (tid < 16)
        invn[tid] = __fdividef(1.0f,
            fmaxf(g_acc[b * 16 + tid] * (1.0f / (float)NV), 1e-8f));
    __syncthreads();

    int pt  = ptbase + tid;
    float x = patches[(long)pt * 3 + 0];
    float y = patches[(long)pt * 3 + 1];
    float z = patches[(long)pt * 3 + 2];

    float sh[N_SH], shell[NUM_SHELLS];
    compute_point(x, y, z, Ys, sh, shell);

    // a[l][s] = shell_s * invn[l*4+s]
    float a[4][4];
#pragma unroll
    for (int l = 0; l < 4; l++)
#pragma unroll
        for (int s = 0; s < 4; s++)
            a[l][s] = shell[s] * invn[l * 4 + s];

    float4* st = &stage4[tid * 17];
#pragma unroll
    for (int i = 0; i < N_SH; i++) {
        const int l = (i == 0) ? 0 : (i < 4) ? 1 : (i < 9) ? 2 : 3;
        st[i] = make_float4(sh[i] * a[l][0], sh[i] * a[l][1],
                            sh[i] * a[l][2], sh[i] * a[l][3]);
    }
    __syncthreads();

    // Coalesced copy: 128 pts * 16 float4 = 2048 float4, 16 per thread.
    float4* ob = (float4*)(out + (long)ptbase * OUT_PER_PT);
#pragma unroll
    for (int k = 0; k < 16; k++) {
        int idx   = k * 128 + tid;
        int point = idx >> 4;
        int j     = idx & 15;
        ob[idx]   = stage4[point * 17 + j];
    }
}

// ---------------------------------------------------------------------------
extern "C" void kernel_launch(void* const* d_in, const int* in_sizes, int n_in,
                              void* d_out, int out_size)
{
    const float* patches = (const float*)d_in[0];
    const float* Y       = (const float*)d_in[1];
    float*       out     = (float*)d_out;

    sh_zero_acc<<<1, BATCH * 16>>>();
    sh_reduce_kernel<<<(BATCH * NV) / 8, 256>>>(patches, Y);
    sh_write_kernel<<<PTS_TOTAL / 128, 128>>>(patches, Y, out);
}